// round 8
// baseline (speedup 1.0000x reference)
#include <cuda_runtime.h>

// decoder_fm: out[b] = 0.5*(sum_k (x@V)_k^2 - sum_j x_j^2*s_j) + x.w + fc_b
//                      + b_users[user[b]] + b_items[item[b]] + 4.0
//
// R8: k-split warp pairs. Even warp of a pair computes lin, x2s, xv[0..3];
// odd warp computes xv[4..9] for the SAME 8 rows (gathers duplicated — DRAM
// is idle, this buys 2x warps at R1's cheap per-row overhead). Each side
// reduces with 2 shfl steps and contributes ONE float per row; combined via
// one smem float + one __syncthreads. All random loads issued before the
// sync. 512 blocks x 256 thr = 4096 warps.

#define PACK2(d, lo, hi)   asm("mov.b64 %0, {%1, %2};" : "=l"(d) : "f"(lo), "f"(hi))
#define UNPACK2(lo, hi, s) asm("mov.b64 {%0, %1}, %2;" : "=f"(lo), "=f"(hi) : "l"(s))
#define FMA2(d, a, b)      asm("fma.rn.f32x2 %0, %1, %2, %3;" : "=l"(d) : "l"(a), "l"(b), "l"(d))
#define ADD2(d, a, b)      asm("add.rn.f32x2 %0, %1, %2;" : "=l"(d) : "l"(a), "l"(b))

__device__ __forceinline__ unsigned long long mk_policy_keep() {
    unsigned long long p;
    asm("createpolicy.fractional.L2::evict_last.b64 %0, 1.0;" : "=l"(p));
    return p;
}
__device__ __forceinline__ float4 ldg_keep4(const float4* p, unsigned long long pol) {
    float4 v;
    asm("ld.global.nc.L2::cache_hint.v4.f32 {%0,%1,%2,%3}, [%4], %5;"
        : "=f"(v.x), "=f"(v.y), "=f"(v.z), "=f"(v.w) : "l"(p), "l"(pol));
    return v;
}
__device__ __forceinline__ float ldg_keep1(const float* p, unsigned long long pol) {
    float v;
    asm("ld.global.nc.L2::cache_hint.f32 %0, [%1], %2;" : "=f"(v) : "l"(p), "l"(pol));
    return v;
}

__global__ __launch_bounds__(256) void fm_kernel(
    const int* __restrict__ user, const int* __restrict__ item,
    const float* __restrict__ user_emb, const float* __restrict__ item_emb,
    const float* __restrict__ fc_w, const float* __restrict__ fc_b,
    const float* __restrict__ fm_V,
    const float* __restrict__ b_users, const float* __restrict__ b_items,
    float* __restrict__ out, int nrows)
{
    __shared__ float2 swsE[128];     // (fc_w[j], s_j)            (even warps)
    __shared__ float2 sVa[2][128];   // V pairs k2=0,1            (even warps)
    __shared__ float2 sVb[3][128];   // V pairs k2=2,3,4          (odd warps)
    __shared__ float  psum[32];      // even-warp partial per row

    const int tid  = threadIdx.x;
    const int lane = tid & 31;
    const int warp = tid >> 5;     // 0..7
    const int pair = warp >> 1;    // 0..3
    const int odd  = warp & 1;     // 0: lin/x2s/xv0..3  1: xv4..9
    const int sub  = lane & 3;     // element slice within a row
    const int rw   = lane >> 2;    // row within warp (0..7)
    const int rowL = pair * 8 + rw;             // 0..31
    const int row  = blockIdx.x * 32 + rowL;
    const bool active = row < nrows;

    const unsigned long long pol = mk_policy_keep();

    // ---- issue ALL random loads up front (overlap with smem staging) ----
    float4 xu[4], xi[4];
    float bu = 0.f, bi = 0.f, fb = 0.f;
    if (active) {
        const int u  = __ldg(user + row);
        const int it = __ldg(item + row);
        const float4* up = reinterpret_cast<const float4*>(user_emb + (long long)u  * 64);
        const float4* ip = reinterpret_cast<const float4*>(item_emb + (long long)it * 64);
        #pragma unroll
        for (int c = 0; c < 4; c++) xu[c] = ldg_keep4(up + c * 4 + sub, pol);
        #pragma unroll
        for (int c = 0; c < 4; c++) xi[c] = ldg_keep4(ip + c * 4 + sub, pol);
        if (!odd) {
            bu = ldg_keep1(b_users + u, pol);
            bi = ldg_keep1(b_items + it, pol);
            fb = __ldg(fc_b);
        }
    }

    // ---- parameter staging ----
    if (tid < 128) {
        float v[10];
        #pragma unroll
        for (int k = 0; k < 10; k++) v[k] = fm_V[tid * 10 + k];
        float s = 0.f;
        #pragma unroll
        for (int k = 0; k < 10; k++) s = fmaf(v[k], v[k], s);
        swsE[tid] = make_float2(fc_w[tid], s);
        sVa[0][tid] = make_float2(v[0], v[1]);
        sVa[1][tid] = make_float2(v[2], v[3]);
        sVb[0][tid] = make_float2(v[4], v[5]);
        sVb[1][tid] = make_float2(v[6], v[7]);
        sVb[2][tid] = make_float2(v[8], v[9]);
    }
    __syncthreads();

    float partial = 0.f;   // this side's contribution to out[row]

    if (active) {
        unsigned long long a0 = 0ull, a1 = 0ull, a2 = 0ull;
        // even: a0=(lin,x2s) a1=xv(0,1) a2=xv(2,3)
        // odd:  a0=xv(4,5)   a1=xv(6,7) a2=xv(8,9)

        #pragma unroll
        for (int h = 0; h < 2; h++) {
            #pragma unroll
            for (int c = 0; c < 4; c++) {
                const float4 xq = h ? xi[c] : xu[c];
                const int j0 = h * 64 + (c * 4 + sub) * 4;
                const float xs[4] = {xq.x, xq.y, xq.z, xq.w};

                if (!odd) {
                    const ulonglong2 wsA = *reinterpret_cast<const ulonglong2*>(&swsE[j0]);
                    const ulonglong2 wsB = *reinterpret_cast<const ulonglong2*>(&swsE[j0 + 2]);
                    const unsigned long long wsp[4] = {wsA.x, wsA.y, wsB.x, wsB.y};
                    const ulonglong2 v0A = *reinterpret_cast<const ulonglong2*>(&sVa[0][j0]);
                    const ulonglong2 v0B = *reinterpret_cast<const ulonglong2*>(&sVa[0][j0 + 2]);
                    const ulonglong2 v1A = *reinterpret_cast<const ulonglong2*>(&sVa[1][j0]);
                    const ulonglong2 v1B = *reinterpret_cast<const ulonglong2*>(&sVa[1][j0 + 2]);
                    const unsigned long long p0[4] = {v0A.x, v0A.y, v0B.x, v0B.y};
                    const unsigned long long p1[4] = {v1A.x, v1A.y, v1B.x, v1B.y};
                    #pragma unroll
                    for (int jj = 0; jj < 4; jj++) {
                        const float x = xs[jj];
                        unsigned long long xp, xsq;
                        PACK2(xsq, x, x * x);
                        PACK2(xp,  x, x);
                        FMA2(a0, xsq, wsp[jj]);   // lin += x*w ; x2s += x^2*s
                        FMA2(a1, xp, p0[jj]);
                        FMA2(a2, xp, p1[jj]);
                    }
                } else {
                    const ulonglong2 v2A = *reinterpret_cast<const ulonglong2*>(&sVb[0][j0]);
                    const ulonglong2 v2B = *reinterpret_cast<const ulonglong2*>(&sVb[0][j0 + 2]);
                    const ulonglong2 v3A = *reinterpret_cast<const ulonglong2*>(&sVb[1][j0]);
                    const ulonglong2 v3B = *reinterpret_cast<const ulonglong2*>(&sVb[1][j0 + 2]);
                    const ulonglong2 v4A = *reinterpret_cast<const ulonglong2*>(&sVb[2][j0]);
                    const ulonglong2 v4B = *reinterpret_cast<const ulonglong2*>(&sVb[2][j0 + 2]);
                    const unsigned long long p2[4] = {v2A.x, v2A.y, v2B.x, v2B.y};
                    const unsigned long long p3[4] = {v3A.x, v3A.y, v3B.x, v3B.y};
                    const unsigned long long p4[4] = {v4A.x, v4A.y, v4B.x, v4B.y};
                    #pragma unroll
                    for (int jj = 0; jj < 4; jj++) {
                        const float x = xs[jj];
                        unsigned long long xp;
                        PACK2(xp, x, x);
                        FMA2(a0, xp, p2[jj]);
                        FMA2(a1, xp, p3[jj]);
                        FMA2(a2, xp, p4[jj]);
                    }
                }
            }
        }

        // reduce across the 4 sub-lanes of this row
        #pragma unroll
        for (int m = 1; m <= 2; m <<= 1) {
            unsigned long long t;
            t = __shfl_xor_sync(0xFFFFFFFFu, a0, m); ADD2(a0, a0, t);
            t = __shfl_xor_sync(0xFFFFFFFFu, a1, m); ADD2(a1, a1, t);
            t = __shfl_xor_sync(0xFFFFFFFFu, a2, m); ADD2(a2, a2, t);
        }

        if (sub == 0) {
            float q0, q1, q2, q3, q4, q5;
            UNPACK2(q0, q1, a1);
            UNPACK2(q2, q3, a2);
            float ssum = q0 * q0;
            ssum = fmaf(q1, q1, ssum);
            ssum = fmaf(q2, q2, ssum);
            ssum = fmaf(q3, q3, ssum);
            if (!odd) {
                UNPACK2(q4, q5, a0);       // lin, x2s
                partial = fmaf(0.5f, ssum - q5, q4) + fb + bu + bi + 4.0f;
            } else {
                UNPACK2(q4, q5, a0);       // xv4, xv5
                ssum = fmaf(q4, q4, ssum);
                ssum = fmaf(q5, q5, ssum);
                partial = 0.5f * ssum;
            }
        }
    }

    // even side publishes, odd side combines + stores
    if (!odd && sub == 0 && active) psum[rowL] = partial;
    __syncthreads();
    if (odd && sub == 0 && active) out[row] = psum[rowL] + partial;
}

extern "C" void kernel_launch(void* const* d_in, const int* in_sizes, int n_in,
                              void* d_out, int out_size)
{
    // metadata order: user, item, u_out, i_out, user_emb, item_emb,
    //                 fc_w, fc_b, fm_V, b_users, b_items
    const int*   user     = (const int*)d_in[0];
    const int*   item     = (const int*)d_in[1];
    const float* user_emb = (const float*)d_in[4];
    const float* item_emb = (const float*)d_in[5];
    const float* fc_w     = (const float*)d_in[6];
    const float* fc_b     = (const float*)d_in[7];
    const float* fm_V     = (const float*)d_in[8];
    const float* b_users  = (const float*)d_in[9];
    const float* b_items  = (const float*)d_in[10];
    float* out = (float*)d_out;

    const int nrows = in_sizes[0];
    const int grid  = (nrows + 31) / 32;   // 32 rows per 256-thread block
    fm_kernel<<<grid, 256>>>(user, item, user_emb, item_emb,
                             fc_w, fc_b, fm_V, b_users, b_items, out, nrows);
}